// round 1
// baseline (speedup 1.0000x reference)
#include <cuda_runtime.h>

#define N_NODES 50000
#define DIM     512
#define N_EDGES 1600000

// ---- scratch (no allocations allowed -> __device__ globals) ----
__device__ float g_y[N_NODES * DIM];       // x @ W^T
__device__ int   g_cnt[N_NODES];
__device__ int   g_start[N_NODES + 1];
__device__ int   g_cursor[N_NODES];
__device__ int   g_scols[N_EDGES];         // cols sorted by row
__device__ float g_svals[N_EDGES];         // vals sorted by row
__device__ float g_colsum[DIM];            // later overwritten with mu[]
__device__ float g_stats[2];               // [0]=sum of squares, [1]=alpha

// ---------------- CSR build ----------------
__global__ void k_zero() {
    int i = blockIdx.x * blockDim.x + threadIdx.x;
    if (i < N_NODES) g_cnt[i] = 0;
    if (i < DIM)     g_colsum[i] = 0.f;
    if (i == 0)      g_stats[0] = 0.f;
}

__global__ void k_hist(const int* __restrict__ rows) {
    int i = blockIdx.x * blockDim.x + threadIdx.x;
    if (i < N_EDGES) atomicAdd(&g_cnt[rows[i]], 1);
}

__global__ void k_scan() {
    __shared__ int sm[1024];
    int t = threadIdx.x;
    const int CH = (N_NODES + 1023) / 1024;    // 49
    int lo = t * CH;
    int hi = min(lo + CH, N_NODES);
    int sum = 0;
    for (int i = lo; i < hi; i++) sum += g_cnt[i];
    sm[t] = sum;
    __syncthreads();
    for (int off = 1; off < 1024; off <<= 1) {
        int v = (t >= off) ? sm[t - off] : 0;
        __syncthreads();
        sm[t] += v;
        __syncthreads();
    }
    int run = sm[t] - sum;   // exclusive prefix
    for (int i = lo; i < hi; i++) {
        g_start[i]  = run;
        g_cursor[i] = run;
        run += g_cnt[i];
    }
    if (t == 1023) g_start[N_NODES] = sm[1023];
}

__global__ void k_scatter(const int* __restrict__ rows,
                          const int* __restrict__ cols,
                          const float* __restrict__ vals) {
    int i = blockIdx.x * blockDim.x + threadIdx.x;
    if (i < N_EDGES) {
        int r = rows[i];
        int p = atomicAdd(&g_cursor[r], 1);
        g_scols[p] = cols[i];
        g_svals[p] = vals[i];
    }
}

// ---------------- GEMM: g_y = x @ W^T ----------------
#define BM 128
#define BN 64
#define BK 16

__global__ __launch_bounds__(256) void k_gemm(const float* __restrict__ X,
                                              const float* __restrict__ W) {
    __shared__ float As[BK][BM];   // As[k][m]
    __shared__ float Bs[BK][BN];   // Bs[k][n]  (n = output col = W row)
    int bm = blockIdx.y * BM;
    int bn = blockIdx.x * BN;
    int tid = threadIdx.x;
    int tx = tid & 15;     // 0..15 -> 4 output cols each
    int ty = tid >> 4;     // 0..15 -> 8 output rows each
    float acc[8][4];
#pragma unroll
    for (int i = 0; i < 8; i++)
#pragma unroll
        for (int j = 0; j < 4; j++) acc[i][j] = 0.f;

    for (int k0 = 0; k0 < DIM; k0 += BK) {
        // A tile: 128 rows x 16 k = 512 float4; 2 per thread
#pragma unroll
        for (int it = 0; it < 2; ++it) {
            int t   = tid + it * 256;
            int row = t >> 2;
            int kq  = (t & 3) << 2;
            int r   = bm + row;
            float4 v = (r < N_NODES) ? *(const float4*)&X[r * DIM + k0 + kq]
                                     : make_float4(0.f, 0.f, 0.f, 0.f);
            As[kq + 0][row] = v.x; As[kq + 1][row] = v.y;
            As[kq + 2][row] = v.z; As[kq + 3][row] = v.w;
        }
        {   // B tile: 64 o x 16 k = 256 float4; 1 per thread
            int o  = tid >> 2;
            int kq = (tid & 3) << 2;
            float4 v = *(const float4*)&W[(bn + o) * DIM + k0 + kq];
            Bs[kq + 0][o] = v.x; Bs[kq + 1][o] = v.y;
            Bs[kq + 2][o] = v.z; Bs[kq + 3][o] = v.w;
        }
        __syncthreads();
#pragma unroll
        for (int k = 0; k < BK; k++) {
            float a[8], b[4];
#pragma unroll
            for (int i = 0; i < 8; i++) a[i] = As[k][ty * 8 + i];
#pragma unroll
            for (int j = 0; j < 4; j++) b[j] = Bs[k][tx * 4 + j];
#pragma unroll
            for (int i = 0; i < 8; i++)
#pragma unroll
                for (int j = 0; j < 4; j++) acc[i][j] += a[i] * b[j];
        }
        __syncthreads();
    }
#pragma unroll
    for (int i = 0; i < 8; i++) {
        int r = bm + ty * 8 + i;
        if (r < N_NODES) {
            float4 v = make_float4(acc[i][0], acc[i][1], acc[i][2], acc[i][3]);
            *(float4*)&g_y[r * DIM + bn + tx * 4] = v;
        }
    }
}

// ---------------- SpMM: Y2[r] = sum_e val * y[col]  (one block per row) ----------------
__global__ __launch_bounds__(128) void k_spmm(float* __restrict__ Y2) {
    int row = blockIdx.x;
    int t = threadIdx.x;
    int s = g_start[row];
    int e = g_start[row + 1];
    int col_off = t * 4;
    float4 acc = make_float4(0.f, 0.f, 0.f, 0.f);
    for (int i = s; i < e; i++) {
        int   c = g_scols[i];
        float v = g_svals[i];
        float4 yv = *(const float4*)&g_y[c * DIM + col_off];
        acc.x += v * yv.x; acc.y += v * yv.y;
        acc.z += v * yv.z; acc.w += v * yv.w;
    }
    *(float4*)&Y2[row * DIM + col_off] = acc;
}

// ---------------- stats: column sums + total sum of squares ----------------
__global__ __launch_bounds__(128) void k_reduce(const float* __restrict__ Y2) {
    int nb = gridDim.x;
    int rows_per = (N_NODES + nb - 1) / nb;
    int r0 = blockIdx.x * rows_per;
    int r1 = min(r0 + rows_per, N_NODES);
    int t = threadIdx.x;
    float4 acc = make_float4(0.f, 0.f, 0.f, 0.f);
    float sq = 0.f;
    for (int r = r0; r < r1; r++) {
        float4 v = *(const float4*)&Y2[r * DIM + t * 4];
        acc.x += v.x; acc.y += v.y; acc.z += v.z; acc.w += v.w;
        sq += v.x * v.x + v.y * v.y + v.z * v.z + v.w * v.w;
    }
    atomicAdd(&g_colsum[t * 4 + 0], acc.x);
    atomicAdd(&g_colsum[t * 4 + 1], acc.y);
    atomicAdd(&g_colsum[t * 4 + 2], acc.z);
    atomicAdd(&g_colsum[t * 4 + 3], acc.w);
#pragma unroll
    for (int off = 16; off; off >>= 1)
        sq += __shfl_xor_sync(0xffffffffu, sq, off);
    if ((t & 31) == 0) atomicAdd(&g_stats[0], sq);
}

__global__ void k_finalize(const float* __restrict__ scale) {
    __shared__ float red[DIM];
    int t = threadIdx.x;
    float cs = g_colsum[t];
    float mu = cs * (1.0f / N_NODES);
    g_colsum[t] = mu;                        // colsum becomes mu[]
    red[t] = cs * mu;                        // = S1^2 / N
    __syncthreads();
    for (int off = DIM / 2; off; off >>= 1) {
        if (t < off) red[t] += red[t + off];
        __syncthreads();
    }
    if (t == 0) {
        float msq = (g_stats[0] - red[0]) * (1.0f / N_NODES);
        g_stats[1] = rsqrtf(msq) * (1.0f + scale[0]) * 22.627416997969522f; // sqrt(512)
    }
}

// ---------------- fused center/scale/relu/residual (in-place on d_out) ----------------
__global__ __launch_bounds__(256) void k_final(const float* __restrict__ X,
                                               float* __restrict__ Out) {
    int i = blockIdx.x * blockDim.x + threadIdx.x;   // float4 index
    if (i >= N_NODES * DIM / 4) return;
    float alpha = g_stats[1];
    int d4 = (i & (DIM / 4 - 1)) * 4;
    float4 mu = *(const float4*)&g_colsum[d4];
    float4 y  = *(const float4*)&Out[i * 4];
    float4 xv = *(const float4*)&X[i * 4];
    float4 o;
    o.x = fmaxf((y.x - mu.x) * alpha, 0.f) + xv.x;
    o.y = fmaxf((y.y - mu.y) * alpha, 0.f) + xv.y;
    o.z = fmaxf((y.z - mu.z) * alpha, 0.f) + xv.z;
    o.w = fmaxf((y.w - mu.w) * alpha, 0.f) + xv.w;
    *(float4*)&Out[i * 4] = o;
}

extern "C" void kernel_launch(void* const* d_in, const int* in_sizes, int n_in,
                              void* d_out, int out_size) {
    const float* x     = (const float*)d_in[0];
    const int*   rows  = (const int*)  d_in[1];
    const int*   cols  = (const int*)  d_in[2];
    const float* vals  = (const float*)d_in[3];
    const float* W     = (const float*)d_in[4];
    const float* scale = (const float*)d_in[5];
    float* out = (float*)d_out;   // doubles as Y2 scratch

    k_zero<<<(N_NODES + 255) / 256, 256>>>();
    k_hist<<<(N_EDGES + 255) / 256, 256>>>(rows);
    k_scan<<<1, 1024>>>();
    k_scatter<<<(N_EDGES + 255) / 256, 256>>>(rows, cols, vals);
    k_gemm<<<dim3(DIM / BN, (N_NODES + BM - 1) / BM), 256>>>(x, W);
    k_spmm<<<N_NODES, 128>>>(out);
    k_reduce<<<512, 128>>>(out);
    k_finalize<<<1, DIM>>>(scale);
    k_final<<<(N_NODES * DIM / 4 + 255) / 256, 256>>>(x, out);
}

// round 3
// speedup vs baseline: 1.3610x; 1.3610x over previous
#include <cuda_runtime.h>
#include <cstdint>

#define N_NODES 50000
#define DIM     512
#define N_EDGES 1600000

// ---- scratch (no allocations allowed -> __device__ globals) ----
__device__ float g_y[N_NODES * DIM];       // x @ W^T
__device__ int   g_cnt[N_NODES];
__device__ int   g_start[N_NODES + 1];
__device__ int   g_cursor[N_NODES];
__device__ int   g_scols[N_EDGES];         // cols sorted by row
__device__ float g_svals[N_EDGES];         // vals sorted by row
__device__ float g_colsum[DIM];            // later overwritten with mu[]
__device__ float g_stats[2];               // [0]=sum of squares, [1]=alpha

// ---------------- CSR build ----------------
__global__ void k_zero() {
    int i = blockIdx.x * blockDim.x + threadIdx.x;
    if (i < N_NODES) g_cnt[i] = 0;
    if (i < DIM)     g_colsum[i] = 0.f;
    if (i == 0)      g_stats[0] = 0.f;
}

__global__ void k_hist(const int* __restrict__ rows) {
    int i = blockIdx.x * blockDim.x + threadIdx.x;
    if (i < N_EDGES) atomicAdd(&g_cnt[rows[i]], 1);
}

__global__ void k_scan() {
    __shared__ int sm[1024];
    int t = threadIdx.x;
    const int CH = (N_NODES + 1023) / 1024;
    int lo = t * CH;
    int hi = min(lo + CH, N_NODES);
    int sum = 0;
    for (int i = lo; i < hi; i++) sum += g_cnt[i];
    sm[t] = sum;
    __syncthreads();
    for (int off = 1; off < 1024; off <<= 1) {
        int v = (t >= off) ? sm[t - off] : 0;
        __syncthreads();
        sm[t] += v;
        __syncthreads();
    }
    int run = sm[t] - sum;
    for (int i = lo; i < hi; i++) {
        g_start[i]  = run;
        g_cursor[i] = run;
        run += g_cnt[i];
    }
    if (t == 1023) g_start[N_NODES] = sm[1023];
}

__global__ void k_scatter(const int* __restrict__ rows,
                          const int* __restrict__ cols,
                          const float* __restrict__ vals) {
    int i = blockIdx.x * blockDim.x + threadIdx.x;
    if (i < N_EDGES) {
        int r = rows[i];
        int p = atomicAdd(&g_cursor[r], 1);
        g_scols[p] = cols[i];
        g_svals[p] = vals[i];
    }
}

// ================= GEMM: g_y = X @ W^T via mma.sync tf32 =================
// CTA tile 128x128x32, 8 warps (2m x 4n), warp tile 64x32.
#define BM 128
#define BN 128
#define BK 32
#define PAD 36                       // float stride (bank-conflict-free)
#define TILE_F4 ((BM * BK) / 4)      // 1024 float4 per tile
#define A_BYTES (BM * PAD * 4)       // 18432
#define BUF_BYTES (2 * A_BYTES)      // A+B per stage = 36864
#define GEMM_SMEM (2 * BUF_BYTES)    // 73728

__device__ __forceinline__ uint32_t smem_u32(const void* p) {
    uint32_t a;
    asm("{ .reg .u64 t; cvta.to.shared.u64 t, %1; cvt.u32.u64 %0, t; }"
        : "=r"(a) : "l"(p));
    return a;
}

#define CP_ASYNC(dst, src, sz) \
    asm volatile("cp.async.cg.shared.global [%0], [%1], 16, %2;" \
                 :: "r"(dst), "l"(src), "r"(sz))
#define CP_COMMIT()  asm volatile("cp.async.commit_group;")
#define CP_WAIT(N)   asm volatile("cp.async.wait_group %0;" :: "n"(N))

__device__ __forceinline__ void mma_tf32(float* d, uint32_t a0, uint32_t a1,
                                         uint32_t a2, uint32_t a3,
                                         uint32_t b0, uint32_t b1) {
    asm volatile(
        "mma.sync.aligned.m16n8k8.row.col.f32.tf32.tf32.f32 "
        "{%0,%1,%2,%3}, {%4,%5,%6,%7}, {%8,%9}, {%0,%1,%2,%3};"
        : "+f"(d[0]), "+f"(d[1]), "+f"(d[2]), "+f"(d[3])
        : "r"(a0), "r"(a1), "r"(a2), "r"(a3), "r"(b0), "r"(b1));
}

__global__ void __launch_bounds__(256)
k_gemm_mma(const float* __restrict__ X, const float* __restrict__ W) {
    extern __shared__ char smem[];
    const int tid  = threadIdx.x;
    const int warp = tid >> 5;
    const int lane = tid & 31;
    const int bm = blockIdx.y * BM;
    const int bn = blockIdx.x * BN;
    const int wm = (warp >> 2) * 64;     // 0 or 64
    const int wn = (warp & 3) * 32;      // 0,32,64,96

    const uint32_t sb = smem_u32(smem);
    // per-thread G->S mapping: 4 float4 for A, 4 for B
    const int frow = tid >> 3;           // 0..31 step (advance 32 rows / iter)
    const int fq   = tid & 7;            // float4-in-row

    float acc[4][4][4];
#pragma unroll
    for (int i = 0; i < 4; i++)
#pragma unroll
        for (int j = 0; j < 4; j++)
#pragma unroll
            for (int k = 0; k < 4; k++) acc[i][j][k] = 0.f;

    // ---- async load of stage s into buffer b ----
    auto issue = [&](int kc, int buf) {
        const int k0 = kc * BK;
        const uint32_t abase = sb + buf * BUF_BYTES;
        const uint32_t bbase = abase + A_BYTES;
#pragma unroll
        for (int it = 0; it < 4; it++) {
            int row = frow + it * 32;
            int r = bm + row;
            uint32_t dst = abase + (row * PAD + fq * 4) * 4;
            const float* src = &X[(size_t)r * DIM + k0 + fq * 4];
            CP_ASYNC(dst, src, (r < N_NODES) ? 16 : 0);
        }
#pragma unroll
        for (int it = 0; it < 4; it++) {
            int row = frow + it * 32;
            uint32_t dst = bbase + (row * PAD + fq * 4) * 4;
            const float* src = &W[(size_t)(bn + row) * DIM + k0 + fq * 4];
            CP_ASYNC(dst, src, 16);
        }
        CP_COMMIT();
    };

    issue(0, 0);

    const int g = lane >> 2;             // group id 0..7
    const int tg = lane & 3;             // thread-in-group

    for (int kc = 0; kc < DIM / BK; kc++) {
        if (kc + 1 < DIM / BK) {
            issue(kc + 1, (kc + 1) & 1);
            CP_WAIT(1);
        } else {
            CP_WAIT(0);
        }
        __syncthreads();
        const float* As = (const float*)(smem + (kc & 1) * BUF_BYTES);
        const float* Bs = As + A_BYTES / 4;
#pragma unroll
        for (int ks = 0; ks < 4; ks++) {
            const int kb = ks * 8;
            uint32_t a[4][4], b[4][2];
#pragma unroll
            for (int mt = 0; mt < 4; mt++) {
                int r0 = wm + mt * 16;
                a[mt][0] = __float_as_uint(As[(r0 + g) * PAD + kb + tg]);
                a[mt][1] = __float_as_uint(As[(r0 + 8 + g) * PAD + kb + tg]);
                a[mt][2] = __float_as_uint(As[(r0 + g) * PAD + kb + 4 + tg]);
                a[mt][3] = __float_as_uint(As[(r0 + 8 + g) * PAD + kb + 4 + tg]);
            }
#pragma unroll
            for (int nt = 0; nt < 4; nt++) {
                int c0 = wn + nt * 8;
                b[nt][0] = __float_as_uint(Bs[(c0 + g) * PAD + kb + tg]);
                b[nt][1] = __float_as_uint(Bs[(c0 + g) * PAD + kb + 4 + tg]);
            }
#pragma unroll
            for (int mt = 0; mt < 4; mt++)
#pragma unroll
                for (int nt = 0; nt < 4; nt++)
                    mma_tf32(acc[mt][nt], a[mt][0], a[mt][1], a[mt][2], a[mt][3],
                             b[nt][0], b[nt][1]);
        }
        __syncthreads();
    }

    // epilogue: each mma tile: thread holds (g, 2*tg), (g, 2*tg+1), (g+8, ...)
#pragma unroll
    for (int mt = 0; mt < 4; mt++) {
#pragma unroll
        for (int nt = 0; nt < 4; nt++) {
            int row = bm + wm + mt * 16 + g;
            int col = bn + wn + nt * 8 + 2 * tg;
            if (row < N_NODES) {
                float2 v0 = make_float2(acc[mt][nt][0], acc[mt][nt][1]);
                *(float2*)&g_y[(size_t)row * DIM + col] = v0;
            }
            if (row + 8 < N_NODES) {
                float2 v1 = make_float2(acc[mt][nt][2], acc[mt][nt][3]);
                *(float2*)&g_y[(size_t)(row + 8) * DIM + col] = v1;
            }
        }
    }
}

// ---------------- SpMM: Y2[r] = sum_e val * y[col]  (one block per row) ----------------
__global__ __launch_bounds__(128) void k_spmm(float* __restrict__ Y2) {
    int row = blockIdx.x;
    int t = threadIdx.x;
    int s = g_start[row];
    int e = g_start[row + 1];
    int col_off = t * 4;
    float4 acc = make_float4(0.f, 0.f, 0.f, 0.f);
    for (int i = s; i < e; i++) {
        int   c = g_scols[i];
        float v = g_svals[i];
        float4 yv = *(const float4*)&g_y[(size_t)c * DIM + col_off];
        acc.x += v * yv.x; acc.y += v * yv.y;
        acc.z += v * yv.z; acc.w += v * yv.w;
    }
    *(float4*)&Y2[(size_t)row * DIM + col_off] = acc;
}

// ---------------- stats: column sums + total sum of squares ----------------
__global__ __launch_bounds__(128) void k_reduce(const float* __restrict__ Y2) {
    int nb = gridDim.x;
    int rows_per = (N_NODES + nb - 1) / nb;
    int r0 = blockIdx.x * rows_per;
    int r1 = min(r0 + rows_per, N_NODES);
    int t = threadIdx.x;
    float4 acc = make_float4(0.f, 0.f, 0.f, 0.f);
    float sq = 0.f;
    for (int r = r0; r < r1; r++) {
        float4 v = *(const float4*)&Y2[(size_t)r * DIM + t * 4];
        acc.x += v.x; acc.y += v.y; acc.z += v.z; acc.w += v.w;
        sq += v.x * v.x + v.y * v.y + v.z * v.z + v.w * v.w;
    }
    atomicAdd(&g_colsum[t * 4 + 0], acc.x);
    atomicAdd(&g_colsum[t * 4 + 1], acc.y);
    atomicAdd(&g_colsum[t * 4 + 2], acc.z);
    atomicAdd(&g_colsum[t * 4 + 3], acc.w);
#pragma unroll
    for (int off = 16; off; off >>= 1)
        sq += __shfl_xor_sync(0xffffffffu, sq, off);
    if ((t & 31) == 0) atomicAdd(&g_stats[0], sq);
}

__global__ void k_finalize(const float* __restrict__ scale) {
    __shared__ float red[DIM];
    int t = threadIdx.x;
    float cs = g_colsum[t];
    float mu = cs * (1.0f / N_NODES);
    g_colsum[t] = mu;
    red[t] = cs * mu;
    __syncthreads();
    for (int off = DIM / 2; off; off >>= 1) {
        if (t < off) red[t] += red[t + off];
        __syncthreads();
    }
    if (t == 0) {
        float msq = (g_stats[0] - red[0]) * (1.0f / N_NODES);
        g_stats[1] = rsqrtf(msq) * (1.0f + scale[0]) * 22.627416997969522f;
    }
}

// ---------------- fused center/scale/relu/residual (in-place on d_out) ----------------
__global__ __launch_bounds__(256) void k_final(const float* __restrict__ X,
                                               float* __restrict__ Out) {
    int i = blockIdx.x * blockDim.x + threadIdx.x;
    if (i >= N_NODES * DIM / 4) return;
    float alpha = g_stats[1];
    int d4 = (i & (DIM / 4 - 1)) * 4;
    float4 mu = *(const float4*)&g_colsum[d4];
    float4 y  = *(const float4*)&Out[i * 4];
    float4 xv = *(const float4*)&X[i * 4];
    float4 o;
    o.x = fmaxf((y.x - mu.x) * alpha, 0.f) + xv.x;
    o.y = fmaxf((y.y - mu.y) * alpha, 0.f) + xv.y;
    o.z = fmaxf((y.z - mu.z) * alpha, 0.f) + xv.z;
    o.w = fmaxf((y.w - mu.w) * alpha, 0.f) + xv.w;
    *(float4*)&Out[i * 4] = o;
}

extern "C" void kernel_launch(void* const* d_in, const int* in_sizes, int n_in,
                              void* d_out, int out_size) {
    const float* x     = (const float*)d_in[0];
    const int*   rows  = (const int*)  d_in[1];
    const int*   cols  = (const int*)  d_in[2];
    const float* vals  = (const float*)d_in[3];
    const float* W     = (const float*)d_in[4];
    const float* scale = (const float*)d_in[5];
    float* out = (float*)d_out;

    cudaFuncSetAttribute(k_gemm_mma, cudaFuncAttributeMaxDynamicSharedMemorySize, GEMM_SMEM);

    k_zero<<<(N_NODES + 255) / 256, 256>>>();
    k_hist<<<(N_EDGES + 255) / 256, 256>>>(rows);
    k_scan<<<1, 1024>>>();
    k_scatter<<<(N_EDGES + 255) / 256, 256>>>(rows, cols, vals);
    k_gemm_mma<<<dim3(DIM / BN, (N_NODES + BM - 1) / BM), 256, GEMM_SMEM>>>(x, W);
    k_spmm<<<N_NODES, 128>>>(out);
    k_reduce<<<512, 128>>>(out);
    k_finalize<<<1, DIM>>>(scale);
    k_final<<<(N_NODES * DIM / 4 + 255) / 256, 256>>>(x, out);
}

// round 5
// speedup vs baseline: 2.1196x; 1.5574x over previous
#include <cuda_runtime.h>
#include <cuda_fp16.h>
#include <cstdint>

#define N_NODES 50000
#define DIM     512
#define N_EDGES 1600000

// ---- scratch (no allocations allowed -> __device__ globals) ----
__device__ __half2 g_yh[N_NODES * DIM / 2]; // x @ W^T in fp16 (SpMM gather source)
__device__ __half2 g_xh[N_NODES * DIM / 2]; // X in fp16 (GEMM A)
__device__ __half2 g_wh[DIM * DIM / 2];     // W in fp16 (GEMM B)
__device__ int   g_cnt[N_NODES];
__device__ int   g_start[N_NODES + 1];
__device__ int   g_cursor[N_NODES];
__device__ int   g_scols[N_EDGES];
__device__ float g_svals[N_EDGES];
__device__ float g_colsum[DIM];            // later overwritten with mu[]
__device__ float g_stats[2];               // [0]=sum of squares, [1]=alpha

// ---------------- CSR build ----------------
__global__ void k_zero() {
    int i = blockIdx.x * blockDim.x + threadIdx.x;
    if (i < N_NODES) g_cnt[i] = 0;
    if (i < DIM)     g_colsum[i] = 0.f;
    if (i == 0)      g_stats[0] = 0.f;
}

__global__ void k_hist(const int* __restrict__ rows) {
    int i = blockIdx.x * blockDim.x + threadIdx.x;
    if (i < N_EDGES) atomicAdd(&g_cnt[rows[i]], 1);
}

__global__ void k_scan() {
    __shared__ int sm[1024];
    int t = threadIdx.x;
    const int CH = (N_NODES + 1023) / 1024;
    int lo = t * CH;
    int hi = min(lo + CH, N_NODES);
    int sum = 0;
    for (int i = lo; i < hi; i++) sum += g_cnt[i];
    sm[t] = sum;
    __syncthreads();
    for (int off = 1; off < 1024; off <<= 1) {
        int v = (t >= off) ? sm[t - off] : 0;
        __syncthreads();
        sm[t] += v;
        __syncthreads();
    }
    int run = sm[t] - sum;
    for (int i = lo; i < hi; i++) {
        g_start[i]  = run;
        g_cursor[i] = run;
        run += g_cnt[i];
    }
    if (t == 1023) g_start[N_NODES] = sm[1023];
}

__global__ void k_scatter(const int* __restrict__ rows,
                          const int* __restrict__ cols,
                          const float* __restrict__ vals) {
    int i = blockIdx.x * blockDim.x + threadIdx.x;
    if (i < N_EDGES) {
        int r = rows[i];
        int p = atomicAdd(&g_cursor[r], 1);
        g_scols[p] = cols[i];
        g_svals[p] = vals[i];
    }
}

// ---------------- fp32 -> fp16 conversion of X and W ----------------
#define NX4 (N_NODES * DIM / 4)
#define NW4 (DIM * DIM / 4)
__global__ __launch_bounds__(256) void k_cvt(const float* __restrict__ X,
                                             const float* __restrict__ W) {
    int i = blockIdx.x * blockDim.x + threadIdx.x;
    if (i < NX4) {
        float4 v = *(const float4*)&X[i * 4];
        __half2 h0 = __floats2half2_rn(v.x, v.y);
        __half2 h1 = __floats2half2_rn(v.z, v.w);
        g_xh[i * 2]     = h0;
        g_xh[i * 2 + 1] = h1;
    } else if (i < NX4 + NW4) {
        int j = i - NX4;
        float4 v = *(const float4*)&W[j * 4];
        __half2 h0 = __floats2half2_rn(v.x, v.y);
        __half2 h1 = __floats2half2_rn(v.z, v.w);
        g_wh[j * 2]     = h0;
        g_wh[j * 2 + 1] = h1;
    }
}

// ================= GEMM: g_yh = X @ W^T via mma.sync f16 =================
// CTA tile 128x128x32(halves), 8 warps (2m x 4n), warp tile 64x32.
#define BM 128
#define BN 128
#define PADH 40                       // half stride per row (80 B)
#define AH_BYTES (128 * PADH * 2)     // 10240
#define BUFH (2 * AH_BYTES)           // 20480 (A+B)
#define GEMM_SMEM (2 * BUFH)          // 40960

__device__ __forceinline__ uint32_t smem_u32(const void* p) {
    uint32_t a;
    asm("{ .reg .u64 t; cvta.to.shared.u64 t, %1; cvt.u32.u64 %0, t; }"
        : "=r"(a) : "l"(p));
    return a;
}

#define CP_ASYNC(dst, src, sz) \
    asm volatile("cp.async.ca.shared.global [%0], [%1], 16, %2;" \
                 :: "r"(dst), "l"(src), "r"(sz))
#define CP_COMMIT()  asm volatile("cp.async.commit_group;")
#define CP_WAIT(N)   asm volatile("cp.async.wait_group %0;" :: "n"(N))

__device__ __forceinline__ void mma_f16(float* d, uint32_t a0, uint32_t a1,
                                        uint32_t a2, uint32_t a3,
                                        uint32_t b0, uint32_t b1) {
    asm volatile(
        "mma.sync.aligned.m16n8k16.row.col.f32.f16.f16.f32 "
        "{%0,%1,%2,%3}, {%4,%5,%6,%7}, {%8,%9}, {%0,%1,%2,%3};"
        : "+f"(d[0]), "+f"(d[1]), "+f"(d[2]), "+f"(d[3])
        : "r"(a0), "r"(a1), "r"(a2), "r"(a3), "r"(b0), "r"(b1));
}

__global__ void __launch_bounds__(256)
k_gemm_h() {
    extern __shared__ char smem[];
    const int tid  = threadIdx.x;
    const int warp = tid >> 5;
    const int lane = tid & 31;
    const int bm = blockIdx.y * BM;
    const int bn = blockIdx.x * BN;
    const int wm = (warp >> 2) * 64;     // 0 or 64
    const int wn = (warp & 3) * 32;      // 0,32,64,96
    const int g  = lane >> 2;            // 0..7
    const int tg = lane & 3;             // 0..3

    const uint32_t sb = smem_u32(smem);
    const int lrow = tid >> 1;           // 0..127 (row in tile)
    const int lpart = tid & 1;           // 32-byte half-row

    const __half* Xh = (const __half*)g_xh;
    const __half* Wh = (const __half*)g_wh;

    float acc[4][4][4];
#pragma unroll
    for (int i = 0; i < 4; i++)
#pragma unroll
        for (int j = 0; j < 4; j++)
#pragma unroll
            for (int k = 0; k < 4; k++) acc[i][j][k] = 0.f;

    auto issue = [&](int kc, int buf) {
        const int k0 = kc * 32;                       // half offset
        const uint32_t abase = sb + buf * BUFH;
        const uint32_t bbase = abase + AH_BYTES;
        {
            int r = bm + lrow;
            uint32_t dst = abase + lrow * (PADH * 2) + lpart * 32;
            const __half* src = &Xh[(size_t)r * DIM + k0 + lpart * 16];
            int ok = (r < N_NODES) ? 16 : 0;
            CP_ASYNC(dst,      src,     ok);
            CP_ASYNC(dst + 16, src + 8, ok);
        }
        {
            uint32_t dst = bbase + lrow * (PADH * 2) + lpart * 32;
            const __half* src = &Wh[(size_t)(bn + lrow) * DIM + k0 + lpart * 16];
            CP_ASYNC(dst,      src,     16);
            CP_ASYNC(dst + 16, src + 8, 16);
        }
        CP_COMMIT();
    };

    issue(0, 0);

    for (int kc = 0; kc < DIM / 32; kc++) {
        if (kc + 1 < DIM / 32) {
            issue(kc + 1, (kc + 1) & 1);
            CP_WAIT(1);
        } else {
            CP_WAIT(0);
        }
        __syncthreads();
        const __half* As = (const __half*)(smem + (kc & 1) * BUFH);
        const __half* Bs = (const __half*)(smem + (kc & 1) * BUFH + AH_BYTES);
#pragma unroll
        for (int ks = 0; ks < 2; ks++) {
            const int kb = ks * 16;                   // half offset in row
            uint32_t a[4][4], b[4][2];
#pragma unroll
            for (int mt = 0; mt < 4; mt++) {
                int r0 = wm + mt * 16;
                a[mt][0] = *(const uint32_t*)&As[(r0 + g)     * PADH + kb + 2 * tg];
                a[mt][1] = *(const uint32_t*)&As[(r0 + 8 + g) * PADH + kb + 2 * tg];
                a[mt][2] = *(const uint32_t*)&As[(r0 + g)     * PADH + kb + 8 + 2 * tg];
                a[mt][3] = *(const uint32_t*)&As[(r0 + 8 + g) * PADH + kb + 8 + 2 * tg];
            }
#pragma unroll
            for (int nt = 0; nt < 4; nt++) {
                int c0 = wn + nt * 8;
                b[nt][0] = *(const uint32_t*)&Bs[(c0 + g) * PADH + kb + 2 * tg];
                b[nt][1] = *(const uint32_t*)&Bs[(c0 + g) * PADH + kb + 8 + 2 * tg];
            }
#pragma unroll
            for (int mt = 0; mt < 4; mt++)
#pragma unroll
                for (int nt = 0; nt < 4; nt++)
                    mma_f16(acc[mt][nt], a[mt][0], a[mt][1], a[mt][2], a[mt][3],
                            b[nt][0], b[nt][1]);
        }
        __syncthreads();
    }

    // epilogue -> fp16 y (g_yh is __half2*, index = (row*DIM+col)/2, col even)
#pragma unroll
    for (int mt = 0; mt < 4; mt++) {
#pragma unroll
        for (int nt = 0; nt < 4; nt++) {
            int row = bm + wm + mt * 16 + g;
            int col = bn + wn + nt * 8 + 2 * tg;
            if (row < N_NODES)
                g_yh[((size_t)row * DIM + col) / 2] =
                    __floats2half2_rn(acc[mt][nt][0], acc[mt][nt][1]);
            if (row + 8 < N_NODES)
                g_yh[((size_t)(row + 8) * DIM + col) / 2] =
                    __floats2half2_rn(acc[mt][nt][2], acc[mt][nt][3]);
        }
    }
}

// ---------------- SpMM: Y2[r] = sum_e val * yh[col]  (one block per row) ----------------
__global__ __launch_bounds__(128) void k_spmm(float* __restrict__ Y2) {
    int row = blockIdx.x;
    int t = threadIdx.x;
    int s = g_start[row];
    int e = g_start[row + 1];
    int h2off = t * 2;                       // __half2 index within row (4 halves)
    float4 acc = make_float4(0.f, 0.f, 0.f, 0.f);
    for (int i = s; i < e; i++) {
        int   c = g_scols[i];
        float v = g_svals[i];
        const __half2* p = &g_yh[(size_t)c * (DIM / 2) + h2off];
        float2 y0 = __half22float2(p[0]);
        float2 y1 = __half22float2(p[1]);
        acc.x += v * y0.x; acc.y += v * y0.y;
        acc.z += v * y1.x; acc.w += v * y1.y;
    }
    *(float4*)&Y2[(size_t)row * DIM + t * 4] = acc;
}

// ---------------- stats: column sums + total sum of squares ----------------
__global__ __launch_bounds__(128) void k_reduce(const float* __restrict__ Y2) {
    int nb = gridDim.x;
    int rows_per = (N_NODES + nb - 1) / nb;
    int r0 = blockIdx.x * rows_per;
    int r1 = min(r0 + rows_per, N_NODES);
    int t = threadIdx.x;
    float4 acc = make_float4(0.f, 0.f, 0.f, 0.f);
    float sq = 0.f;
    for (int r = r0; r < r1; r++) {
        float4 v = *(const float4*)&Y2[(size_t)r * DIM + t * 4];
        acc.x += v.x; acc.y += v.y; acc.z += v.z; acc.w += v.w;
        sq += v.x * v.x + v.y * v.y + v.z * v.z + v.w * v.w;
    }
    atomicAdd(&g_colsum[t * 4 + 0], acc.x);
    atomicAdd(&g_colsum[t * 4 + 1], acc.y);
    atomicAdd(&g_colsum[t * 4 + 2], acc.z);
    atomicAdd(&g_colsum[t * 4 + 3], acc.w);
#pragma unroll
    for (int off = 16; off; off >>= 1)
        sq += __shfl_xor_sync(0xffffffffu, sq, off);
    if ((t & 31) == 0) atomicAdd(&g_stats[0], sq);
}

__global__ void k_finalize(const float* __restrict__ scale) {
    __shared__ float red[DIM];
    int t = threadIdx.x;
    float cs = g_colsum[t];
    float mu = cs * (1.0f / N_NODES);
    g_colsum[t] = mu;
    red[t] = cs * mu;
    __syncthreads();
    for (int off = DIM / 2; off; off >>= 1) {
        if (t < off) red[t] += red[t + off];
        __syncthreads();
    }
    if (t == 0) {
        float msq = (g_stats[0] - red[0]) * (1.0f / N_NODES);
        g_stats[1] = rsqrtf(msq) * (1.0f + scale[0]) * 22.627416997969522f;
    }
}

// ---------------- fused center/scale/relu/residual (in-place on d_out) ----------------
__global__ __launch_bounds__(256) void k_final(const float* __restrict__ X,
                                               float* __restrict__ Out) {
    int i = blockIdx.x * blockDim.x + threadIdx.x;
    if (i >= N_NODES * DIM / 4) return;
    float alpha = g_stats[1];
    int d4 = (i & (DIM / 4 - 1)) * 4;
    float4 mu = *(const float4*)&g_colsum[d4];
    float4 y  = *(const float4*)&Out[i * 4];
    float4 xv = *(const float4*)&X[i * 4];
    float4 o;
    o.x = fmaxf((y.x - mu.x) * alpha, 0.f) + xv.x;
    o.y = fmaxf((y.y - mu.y) * alpha, 0.f) + xv.y;
    o.z = fmaxf((y.z - mu.z) * alpha, 0.f) + xv.z;
    o.w = fmaxf((y.w - mu.w) * alpha, 0.f) + xv.w;
    *(float4*)&Out[i * 4] = o;
}

extern "C" void kernel_launch(void* const* d_in, const int* in_sizes, int n_in,
                              void* d_out, int out_size) {
    const float* x     = (const float*)d_in[0];
    const int*   rows  = (const int*)  d_in[1];
    const int*   cols  = (const int*)  d_in[2];
    const float* vals  = (const float*)d_in[3];
    const float* W     = (const float*)d_in[4];
    const float* scale = (const float*)d_in[5];
    float* out = (float*)d_out;

    k_zero<<<(N_NODES + 255) / 256, 256>>>();
    k_hist<<<(N_EDGES + 255) / 256, 256>>>(rows);
    k_scan<<<1, 1024>>>();
    k_scatter<<<(N_EDGES + 255) / 256, 256>>>(rows, cols, vals);
    k_cvt<<<(NX4 + NW4 + 255) / 256, 256>>>(x, W);
    k_gemm_h<<<dim3(DIM / BN, (N_NODES + BM - 1) / BM), 256, GEMM_SMEM>>>();
    k_spmm<<<N_NODES, 128>>>(out);
    k_reduce<<<512, 128>>>(out);
    k_finalize<<<1, DIM>>>(scale);
    k_final<<<(N_NODES * DIM / 4 + 255) / 256, 256>>>(x, out);
}

// round 6
// speedup vs baseline: 2.2265x; 1.0504x over previous
#include <cuda_runtime.h>
#include <cuda_fp16.h>
#include <cstdint>

#define N_NODES 50000
#define DIM     512
#define N_EDGES 1600000

// ---- scratch (no allocations allowed -> __device__ globals) ----
__device__ __half2 g_yh[N_NODES * DIM / 2]; // x @ W^T in fp16 (SpMM gather source)
__device__ __half2 g_xh[N_NODES * DIM / 2]; // X in fp16 (GEMM A)
__device__ __half2 g_wh[DIM * DIM / 2];     // W in fp16 (GEMM B)
__device__ int   g_cnt[N_NODES];
__device__ int   g_start[N_NODES + 1];
__device__ int   g_cursor[N_NODES];
__device__ int2  g_edges[N_EDGES];          // packed (col, val_bits), row-sorted
__device__ float g_colsum[DIM];             // later overwritten with mu[]
__device__ float g_stats[2];                // [0]=sum of squares, [1]=alpha

// ---------------- CSR build ----------------
__global__ void k_zero() {
    int i = blockIdx.x * blockDim.x + threadIdx.x;
    if (i < N_NODES) g_cnt[i] = 0;
}

__global__ void k_hist(const int* __restrict__ rows) {
    int i = blockIdx.x * blockDim.x + threadIdx.x;
    if (i < N_EDGES) atomicAdd(&g_cnt[rows[i]], 1);
}

__global__ void k_scan() {
    __shared__ int sm[1024];
    int t = threadIdx.x;
    if (t < DIM) g_colsum[t] = 0.f;          // zero stats here (used much later)
    if (t == 0)  g_stats[0] = 0.f;
    const int CH = (N_NODES + 1023) / 1024;
    int lo = t * CH;
    int hi = min(lo + CH, N_NODES);
    int sum = 0;
    for (int i = lo; i < hi; i++) sum += g_cnt[i];
    sm[t] = sum;
    __syncthreads();
    for (int off = 1; off < 1024; off <<= 1) {
        int v = (t >= off) ? sm[t - off] : 0;
        __syncthreads();
        sm[t] += v;
        __syncthreads();
    }
    int run = sm[t] - sum;
    for (int i = lo; i < hi; i++) {
        g_start[i]  = run;
        g_cursor[i] = run;
        run += g_cnt[i];
    }
    if (t == 1023) g_start[N_NODES] = sm[1023];
}

__global__ void k_scatter(const int* __restrict__ rows,
                          const int* __restrict__ cols,
                          const float* __restrict__ vals) {
    int i = blockIdx.x * blockDim.x + threadIdx.x;
    if (i < N_EDGES) {
        int r = rows[i];
        int p = atomicAdd(&g_cursor[r], 1);
        g_edges[p] = make_int2(cols[i], __float_as_int(vals[i]));
    }
}

// ---------------- fp32 -> fp16 conversion of X and W ----------------
#define NX4 (N_NODES * DIM / 4)
#define NW4 (DIM * DIM / 4)
__global__ __launch_bounds__(256) void k_cvt(const float* __restrict__ X,
                                             const float* __restrict__ W) {
    int i = blockIdx.x * blockDim.x + threadIdx.x;
    if (i < NX4) {
        float4 v = *(const float4*)&X[i * 4];
        g_xh[i * 2]     = __floats2half2_rn(v.x, v.y);
        g_xh[i * 2 + 1] = __floats2half2_rn(v.z, v.w);
    } else if (i < NX4 + NW4) {
        int j = i - NX4;
        float4 v = *(const float4*)&W[j * 4];
        g_wh[j * 2]     = __floats2half2_rn(v.x, v.y);
        g_wh[j * 2 + 1] = __floats2half2_rn(v.z, v.w);
    }
}

// ================= GEMM: g_yh = X @ W^T via mma.sync f16 + ldmatrix =================
// CTA tile 128x128x32(halves), 8 warps (2m x 4n), warp tile 64x32.
#define BM 128
#define BN 128
#define PADH 40                       // half stride per row (80 B, ldmatrix conflict-free)
#define AH_BYTES (128 * PADH * 2)     // 10240
#define BUFH (2 * AH_BYTES)           // 20480 (A+B)
#define GEMM_SMEM (2 * BUFH)          // 40960

__device__ __forceinline__ uint32_t smem_u32(const void* p) {
    uint32_t a;
    asm("{ .reg .u64 t; cvta.to.shared.u64 t, %1; cvt.u32.u64 %0, t; }"
        : "=r"(a) : "l"(p));
    return a;
}

#define CP_ASYNC(dst, src, sz) \
    asm volatile("cp.async.ca.shared.global [%0], [%1], 16, %2;" \
                 :: "r"(dst), "l"(src), "r"(sz))
#define CP_COMMIT()  asm volatile("cp.async.commit_group;")
#define CP_WAIT(N)   asm volatile("cp.async.wait_group %0;" :: "n"(N))

#define LDSM_X4(r0, r1, r2, r3, addr) \
    asm volatile("ldmatrix.sync.aligned.m8n8.x4.shared.b16 {%0,%1,%2,%3}, [%4];" \
                 : "=r"(r0), "=r"(r1), "=r"(r2), "=r"(r3) : "r"(addr))

__device__ __forceinline__ void mma_f16(float* d, uint32_t a0, uint32_t a1,
                                        uint32_t a2, uint32_t a3,
                                        uint32_t b0, uint32_t b1) {
    asm volatile(
        "mma.sync.aligned.m16n8k16.row.col.f32.f16.f16.f32 "
        "{%0,%1,%2,%3}, {%4,%5,%6,%7}, {%8,%9}, {%0,%1,%2,%3};"
        : "+f"(d[0]), "+f"(d[1]), "+f"(d[2]), "+f"(d[3])
        : "r"(a0), "r"(a1), "r"(a2), "r"(a3), "r"(b0), "r"(b1));
}

__global__ void __launch_bounds__(256)
k_gemm_h() {
    extern __shared__ char smem[];
    const int tid  = threadIdx.x;
    const int warp = tid >> 5;
    const int lane = tid & 31;
    const int bm = blockIdx.y * BM;
    const int bn = blockIdx.x * BN;
    const int wm = (warp >> 2) * 64;     // 0 or 64
    const int wn = (warp & 3) * 32;      // 0,32,64,96
    const int g  = lane >> 2;            // 0..7
    const int tg = lane & 3;             // 0..3

    const uint32_t sb = smem_u32(smem);
    const int lrow = tid >> 1;           // 0..127 (row in tile)
    const int lpart = tid & 1;           // 32-byte half-row

    // ldmatrix lane->address mapping (within a 16x16 A block / 8x16 B block pair)
    const int lm_row = lane & 15;        // row 0..15
    const int lm_k   = (lane >> 4) * 8;  // k-offset 0 or 8
    const int bl_row = lane & 7;         // B: n-row 0..7
    const int bl_sel = (lane >> 3) & 1;  // B: k half 0/8
    const int bl_nt  = (lane >> 4) & 1;  // B: nt sub-tile 0/1

    const __half* Xh = (const __half*)g_xh;
    const __half* Wh = (const __half*)g_wh;

    float acc[4][4][4];
#pragma unroll
    for (int i = 0; i < 4; i++)
#pragma unroll
        for (int j = 0; j < 4; j++)
#pragma unroll
            for (int k = 0; k < 4; k++) acc[i][j][k] = 0.f;

    auto issue = [&](int kc, int buf) {
        const int k0 = kc * 32;                       // half offset
        const uint32_t abase = sb + buf * BUFH;
        const uint32_t bbase = abase + AH_BYTES;
        {
            int r = bm + lrow;
            uint32_t dst = abase + lrow * (PADH * 2) + lpart * 32;
            const __half* src = &Xh[(size_t)r * DIM + k0 + lpart * 16];
            int ok = (r < N_NODES) ? 16 : 0;
            CP_ASYNC(dst,      src,     ok);
            CP_ASYNC(dst + 16, src + 8, ok);
        }
        {
            uint32_t dst = bbase + lrow * (PADH * 2) + lpart * 32;
            const __half* src = &Wh[(size_t)(bn + lrow) * DIM + k0 + lpart * 16];
            CP_ASYNC(dst,      src,     16);
            CP_ASYNC(dst + 16, src + 8, 16);
        }
        CP_COMMIT();
    };

    issue(0, 0);

    for (int kc = 0; kc < DIM / 32; kc++) {
        if (kc + 1 < DIM / 32) {
            issue(kc + 1, (kc + 1) & 1);
            CP_WAIT(1);
        } else {
            CP_WAIT(0);
        }
        __syncthreads();
        const uint32_t abuf = sb + (kc & 1) * BUFH;
        const uint32_t bbuf = abuf + AH_BYTES;
#pragma unroll
        for (int ks = 0; ks < 2; ks++) {
            const int kb = ks * 16;                   // half offset in row
            uint32_t a[4][4], b[4][2];
#pragma unroll
            for (int mt = 0; mt < 4; mt++) {
                // A 16x16 block at rows wm+mt*16, k kb..kb+15
                uint32_t addr = abuf +
                    ((wm + mt * 16 + lm_row) * PADH + kb + lm_k) * 2;
                LDSM_X4(a[mt][0], a[mt][1], a[mt][2], a[mt][3], addr);
            }
#pragma unroll
            for (int np = 0; np < 2; np++) {
                // B: two 8x16 n-tiles per ldmatrix.x4:
                // matrices: (nt=2np, k0),(nt=2np, k8),(nt=2np+1, k0),(nt=2np+1, k8)
                int n0 = wn + (2 * np + bl_nt) * 8 + bl_row;
                uint32_t addr = bbuf + (n0 * PADH + kb + bl_sel * 8) * 2;
                LDSM_X4(b[2 * np][0], b[2 * np][1],
                        b[2 * np + 1][0], b[2 * np + 1][1], addr);
            }
#pragma unroll
            for (int mt = 0; mt < 4; mt++)
#pragma unroll
                for (int nt = 0; nt < 4; nt++)
                    mma_f16(acc[mt][nt], a[mt][0], a[mt][1], a[mt][2], a[mt][3],
                            b[nt][0], b[nt][1]);
        }
        __syncthreads();
    }

    // epilogue -> fp16 y
#pragma unroll
    for (int mt = 0; mt < 4; mt++) {
#pragma unroll
        for (int nt = 0; nt < 4; nt++) {
            int row = bm + wm + mt * 16 + g;
            int col = bn + wn + nt * 8 + 2 * tg;
            if (row < N_NODES)
                g_yh[((size_t)row * DIM + col) / 2] =
                    __floats2half2_rn(acc[mt][nt][0], acc[mt][nt][1]);
            if (row + 8 < N_NODES)
                g_yh[((size_t)(row + 8) * DIM + col) / 2] =
                    __floats2half2_rn(acc[mt][nt][2], acc[mt][nt][3]);
        }
    }
}

// ---------------- SpMM: Y2[r] = sum_e val * yh[col]  (one block per row) ----------------
__global__ __launch_bounds__(128) void k_spmm(float* __restrict__ Y2) {
    int row = blockIdx.x;
    int t = threadIdx.x;
    int s = g_start[row];
    int e = g_start[row + 1];
    int h2off = t * 2;
    float4 acc0 = make_float4(0.f, 0.f, 0.f, 0.f);
    float4 acc1 = make_float4(0.f, 0.f, 0.f, 0.f);
    int i = s;
    for (; i + 1 < e; i += 2) {
        int2 e0 = __ldg(&g_edges[i]);
        int2 e1 = __ldg(&g_edges[i + 1]);
        float v0 = __int_as_float(e0.y);
        float v1 = __int_as_float(e1.y);
        const __half2* p0 = &g_yh[(size_t)e0.x * (DIM / 2) + h2off];
        const __half2* p1 = &g_yh[(size_t)e1.x * (DIM / 2) + h2off];
        float2 a0 = __half22float2(p0[0]);
        float2 a1 = __half22float2(p0[1]);
        float2 b0 = __half22float2(p1[0]);
        float2 b1 = __half22float2(p1[1]);
        acc0.x += v0 * a0.x; acc0.y += v0 * a0.y;
        acc0.z += v0 * a1.x; acc0.w += v0 * a1.y;
        acc1.x += v1 * b0.x; acc1.y += v1 * b0.y;
        acc1.z += v1 * b1.x; acc1.w += v1 * b1.y;
    }
    if (i < e) {
        int2 e0 = __ldg(&g_edges[i]);
        float v0 = __int_as_float(e0.y);
        const __half2* p0 = &g_yh[(size_t)e0.x * (DIM / 2) + h2off];
        float2 a0 = __half22float2(p0[0]);
        float2 a1 = __half22float2(p0[1]);
        acc0.x += v0 * a0.x; acc0.y += v0 * a0.y;
        acc0.z += v0 * a1.x; acc0.w += v0 * a1.y;
    }
    acc0.x += acc1.x; acc0.y += acc1.y; acc0.z += acc1.z; acc0.w += acc1.w;
    *(float4*)&Y2[(size_t)row * DIM + t * 4] = acc0;
}

// ---------------- stats: column sums + total sum of squares ----------------
__global__ __launch_bounds__(128) void k_reduce(const float* __restrict__ Y2) {
    int nb = gridDim.x;
    int rows_per = (N_NODES + nb - 1) / nb;
    int r0 = blockIdx.x * rows_per;
    int r1 = min(r0 + rows_per, N_NODES);
    int t = threadIdx.x;
    float4 acc = make_float4(0.f, 0.f, 0.f, 0.f);
    float sq = 0.f;
    for (int r = r0; r < r1; r++) {
        float4 v = *(const float4*)&Y2[(size_t)r * DIM + t * 4];
        acc.x += v.x; acc.y += v.y; acc.z += v.z; acc.w += v.w;
        sq += v.x * v.x + v.y * v.y + v.z * v.z + v.w * v.w;
    }
    atomicAdd(&g_colsum[t * 4 + 0], acc.x);
    atomicAdd(&g_colsum[t * 4 + 1], acc.y);
    atomicAdd(&g_colsum[t * 4 + 2], acc.z);
    atomicAdd(&g_colsum[t * 4 + 3], acc.w);
#pragma unroll
    for (int off = 16; off; off >>= 1)
        sq += __shfl_xor_sync(0xffffffffu, sq, off);
    if ((t & 31) == 0) atomicAdd(&g_stats[0], sq);
}

__global__ void k_finalize(const float* __restrict__ scale) {
    __shared__ float red[DIM];
    int t = threadIdx.x;
    float cs = g_colsum[t];
    float mu = cs * (1.0f / N_NODES);
    g_colsum[t] = mu;
    red[t] = cs * mu;
    __syncthreads();
    for (int off = DIM / 2; off; off >>= 1) {
        if (t < off) red[t] += red[t + off];
        __syncthreads();
    }
    if (t == 0) {
        float msq = (g_stats[0] - red[0]) * (1.0f / N_NODES);
        g_stats[1] = rsqrtf(msq) * (1.0f + scale[0]) * 22.627416997969522f;
    }
}

// ---------------- fused center/scale/relu/residual (in-place on d_out) ----------------
__global__ __launch_bounds__(256) void k_final(const float* __restrict__ X,
                                               float* __restrict__ Out) {
    int i = blockIdx.x * blockDim.x + threadIdx.x;
    if (i >= N_NODES * DIM / 4) return;
    float alpha = g_stats[1];
    int d4 = (i & (DIM / 4 - 1)) * 4;
    float4 mu = *(const float4*)&g_colsum[d4];
    float4 y  = *(const float4*)&Out[i * 4];
    float4 xv = *(const float4*)&X[i * 4];
    float4 o;
    o.x = fmaxf((y.x - mu.x) * alpha, 0.f) + xv.x;
    o.y = fmaxf((y.y - mu.y) * alpha, 0.f) + xv.y;
    o.z = fmaxf((y.z - mu.z) * alpha, 0.f) + xv.z;
    o.w = fmaxf((y.w - mu.w) * alpha, 0.f) + xv.w;
    *(float4*)&Out[i * 4] = o;
}

extern "C" void kernel_launch(void* const* d_in, const int* in_sizes, int n_in,
                              void* d_out, int out_size) {
    const float* x     = (const float*)d_in[0];
    const int*   rows  = (const int*)  d_in[1];
    const int*   cols  = (const int*)  d_in[2];
    const float* vals  = (const float*)d_in[3];
    const float* W     = (const float*)d_in[4];
    const float* scale = (const float*)d_in[5];
    float* out = (float*)d_out;

    k_zero<<<(N_NODES + 255) / 256, 256>>>();
    k_hist<<<(N_EDGES + 255) / 256, 256>>>(rows);
    k_scan<<<1, 1024>>>();
    k_scatter<<<(N_EDGES + 255) / 256, 256>>>(rows, cols, vals);
    k_cvt<<<(NX4 + NW4 + 255) / 256, 256>>>(x, W);
    k_gemm_h<<<dim3(DIM / BN, (N_NODES + BM - 1) / BM), 256, GEMM_SMEM>>>();
    k_spmm<<<N_NODES, 128>>>(out);
    k_reduce<<<512, 128>>>(out);
    k_finalize<<<1, DIM>>>(scale);
    k_final<<<(N_NODES * DIM / 4 + 255) / 256, 256>>>(x, out);
}

// round 7
// speedup vs baseline: 2.2660x; 1.0177x over previous
#include <cuda_runtime.h>
#include <cuda_fp16.h>
#include <cstdint>

#define N_NODES 50000
#define DIM     512
#define N_EDGES 1600000

// ---- scratch (no allocations allowed -> __device__ globals) ----
__device__ __half2 g_yh[N_NODES * DIM / 2]; // x @ W^T in fp16 (SpMM gather source)
__device__ __half2 g_xh[N_NODES * DIM / 2]; // X fp16 (GEMM A); reused as fp16 Y2 after GEMM
__device__ __half2 g_wh[DIM * DIM / 2];     // W in fp16 (GEMM B)
__device__ int   g_cnt[N_NODES];
__device__ int   g_start[N_NODES + 1];
__device__ int   g_cursor[N_NODES];
__device__ int2  g_edges[N_EDGES];          // packed (col, val_bits), row-sorted
__device__ float g_colsum[DIM];             // later overwritten with mu[]
__device__ float g_stats[2];                // [0]=sum of squares, [1]=alpha

// ---------------- CSR build ----------------
__global__ void k_zero() {
    int i = blockIdx.x * blockDim.x + threadIdx.x;
    if (i < N_NODES) g_cnt[i] = 0;
    if (i < DIM)     g_colsum[i] = 0.f;
    if (i == 0)      g_stats[0] = 0.f;
}

__global__ void k_hist(const int* __restrict__ rows) {
    int i = blockIdx.x * blockDim.x + threadIdx.x;
    if (i < N_EDGES) atomicAdd(&g_cnt[rows[i]], 1);
}

__global__ void k_scan() {
    __shared__ int sm[1024];
    int t = threadIdx.x;
    const int CH = (N_NODES + 1023) / 1024;
    int lo = t * CH;
    int hi = min(lo + CH, N_NODES);
    int sum = 0;
    for (int i = lo; i < hi; i++) sum += g_cnt[i];
    sm[t] = sum;
    __syncthreads();
    for (int off = 1; off < 1024; off <<= 1) {
        int v = (t >= off) ? sm[t - off] : 0;
        __syncthreads();
        sm[t] += v;
        __syncthreads();
    }
    int run = sm[t] - sum;
    for (int i = lo; i < hi; i++) {
        g_start[i]  = run;
        g_cursor[i] = run;
        run += g_cnt[i];
    }
    if (t == 1023) g_start[N_NODES] = sm[1023];
}

__global__ void k_scatter(const int* __restrict__ rows,
                          const int* __restrict__ cols,
                          const float* __restrict__ vals) {
    int i = blockIdx.x * blockDim.x + threadIdx.x;
    if (i < N_EDGES) {
        int r = rows[i];
        int p = atomicAdd(&g_cursor[r], 1);
        g_edges[p] = make_int2(cols[i], __float_as_int(vals[i]));
    }
}

// ---------------- fp32 -> fp16 conversion of X and W ----------------
#define NX4 (N_NODES * DIM / 4)
#define NW4 (DIM * DIM / 4)
__global__ __launch_bounds__(256) void k_cvt(const float* __restrict__ X,
                                             const float* __restrict__ W) {
    int i = blockIdx.x * blockDim.x + threadIdx.x;
    if (i < NX4) {
        float4 v = *(const float4*)&X[i * 4];
        g_xh[i * 2]     = __floats2half2_rn(v.x, v.y);
        g_xh[i * 2 + 1] = __floats2half2_rn(v.z, v.w);
    } else if (i < NX4 + NW4) {
        int j = i - NX4;
        float4 v = *(const float4*)&W[j * 4];
        g_wh[j * 2]     = __floats2half2_rn(v.x, v.y);
        g_wh[j * 2 + 1] = __floats2half2_rn(v.z, v.w);
    }
}

// ================= GEMM: g_yh = X @ W^T via mma.sync f16 + ldmatrix =================
#define BM 128
#define BN 128
#define PADH 40
#define AH_BYTES (128 * PADH * 2)
#define BUFH (2 * AH_BYTES)
#define GEMM_SMEM (2 * BUFH)

__device__ __forceinline__ uint32_t smem_u32(const void* p) {
    uint32_t a;
    asm("{ .reg .u64 t; cvta.to.shared.u64 t, %1; cvt.u32.u64 %0, t; }"
        : "=r"(a) : "l"(p));
    return a;
}

#define CP_ASYNC(dst, src, sz) \
    asm volatile("cp.async.ca.shared.global [%0], [%1], 16, %2;" \
                 :: "r"(dst), "l"(src), "r"(sz))
#define CP_COMMIT()  asm volatile("cp.async.commit_group;")
#define CP_WAIT(N)   asm volatile("cp.async.wait_group %0;" :: "n"(N))

#define LDSM_X4(r0, r1, r2, r3, addr) \
    asm volatile("ldmatrix.sync.aligned.m8n8.x4.shared.b16 {%0,%1,%2,%3}, [%4];" \
                 : "=r"(r0), "=r"(r1), "=r"(r2), "=r"(r3) : "r"(addr))

__device__ __forceinline__ void mma_f16(float* d, uint32_t a0, uint32_t a1,
                                        uint32_t a2, uint32_t a3,
                                        uint32_t b0, uint32_t b1) {
    asm volatile(
        "mma.sync.aligned.m16n8k16.row.col.f32.f16.f16.f32 "
        "{%0,%1,%2,%3}, {%4,%5,%6,%7}, {%8,%9}, {%0,%1,%2,%3};"
        : "+f"(d[0]), "+f"(d[1]), "+f"(d[2]), "+f"(d[3])
        : "r"(a0), "r"(a1), "r"(a2), "r"(a3), "r"(b0), "r"(b1));
}

__global__ void __launch_bounds__(256)
k_gemm_h() {
    extern __shared__ char smem[];
    const int tid  = threadIdx.x;
    const int warp = tid >> 5;
    const int lane = tid & 31;
    const int bm = blockIdx.y * BM;
    const int bn = blockIdx.x * BN;
    const int wm = (warp >> 2) * 64;
    const int wn = (warp & 3) * 32;
    const int g  = lane >> 2;
    const int tg = lane & 3;

    const uint32_t sb = smem_u32(smem);
    const int lrow = tid >> 1;
    const int lpart = tid & 1;

    const int lm_row = lane & 15;
    const int lm_k   = (lane >> 4) * 8;
    const int bl_row = lane & 7;
    const int bl_sel = (lane >> 3) & 1;
    const int bl_nt  = (lane >> 4) & 1;

    const __half* Xh = (const __half*)g_xh;
    const __half* Wh = (const __half*)g_wh;

    float acc[4][4][4];
#pragma unroll
    for (int i = 0; i < 4; i++)
#pragma unroll
        for (int j = 0; j < 4; j++)
#pragma unroll
            for (int k = 0; k < 4; k++) acc[i][j][k] = 0.f;

    auto issue = [&](int kc, int buf) {
        const int k0 = kc * 32;
        const uint32_t abase = sb + buf * BUFH;
        const uint32_t bbase = abase + AH_BYTES;
        {
            int r = bm + lrow;
            uint32_t dst = abase + lrow * (PADH * 2) + lpart * 32;
            const __half* src = &Xh[(size_t)r * DIM + k0 + lpart * 16];
            int ok = (r < N_NODES) ? 16 : 0;
            CP_ASYNC(dst,      src,     ok);
            CP_ASYNC(dst + 16, src + 8, ok);
        }
        {
            uint32_t dst = bbase + lrow * (PADH * 2) + lpart * 32;
            const __half* src = &Wh[(size_t)(bn + lrow) * DIM + k0 + lpart * 16];
            CP_ASYNC(dst,      src,     16);
            CP_ASYNC(dst + 16, src + 8, 16);
        }
        CP_COMMIT();
    };

    issue(0, 0);

    for (int kc = 0; kc < DIM / 32; kc++) {
        if (kc + 1 < DIM / 32) {
            issue(kc + 1, (kc + 1) & 1);
            CP_WAIT(1);
        } else {
            CP_WAIT(0);
        }
        __syncthreads();
        const uint32_t abuf = sb + (kc & 1) * BUFH;
        const uint32_t bbuf = abuf + AH_BYTES;
#pragma unroll
        for (int ks = 0; ks < 2; ks++) {
            const int kb = ks * 16;
            uint32_t a[4][4], b[4][2];
#pragma unroll
            for (int mt = 0; mt < 4; mt++) {
                uint32_t addr = abuf +
                    ((wm + mt * 16 + lm_row) * PADH + kb + lm_k) * 2;
                LDSM_X4(a[mt][0], a[mt][1], a[mt][2], a[mt][3], addr);
            }
#pragma unroll
            for (int np = 0; np < 2; np++) {
                int n0 = wn + (2 * np + bl_nt) * 8 + bl_row;
                uint32_t addr = bbuf + (n0 * PADH + kb + bl_sel * 8) * 2;
                LDSM_X4(b[2 * np][0], b[2 * np][1],
                        b[2 * np + 1][0], b[2 * np + 1][1], addr);
            }
#pragma unroll
            for (int mt = 0; mt < 4; mt++)
#pragma unroll
                for (int nt = 0; nt < 4; nt++)
                    mma_f16(acc[mt][nt], a[mt][0], a[mt][1], a[mt][2], a[mt][3],
                            b[nt][0], b[nt][1]);
        }
        __syncthreads();
    }

#pragma unroll
    for (int mt = 0; mt < 4; mt++) {
#pragma unroll
        for (int nt = 0; nt < 4; nt++) {
            int row = bm + wm + mt * 16 + g;
            int col = bn + wn + nt * 8 + 2 * tg;
            if (row < N_NODES)
                g_yh[((size_t)row * DIM + col) / 2] =
                    __floats2half2_rn(acc[mt][nt][0], acc[mt][nt][1]);
            if (row + 8 < N_NODES)
                g_yh[((size_t)(row + 8) * DIM + col) / 2] =
                    __floats2half2_rn(acc[mt][nt][2], acc[mt][nt][3]);
        }
    }
}

// ---------------- SpMM: Y2fp16[r] = sum_e val * yh[col] (writes into g_xh) ----------------
__global__ __launch_bounds__(128) void k_spmm() {
    int row = blockIdx.x;
    int t = threadIdx.x;
    int s = g_start[row];
    int e = g_start[row + 1];
    int h2off = t * 2;
    float4 acc0 = make_float4(0.f, 0.f, 0.f, 0.f);
    float4 acc1 = make_float4(0.f, 0.f, 0.f, 0.f);
    int i = s;
    for (; i + 1 < e; i += 2) {
        int2 e0 = __ldg(&g_edges[i]);
        int2 e1 = __ldg(&g_edges[i + 1]);
        float v0 = __int_as_float(e0.y);
        float v1 = __int_as_float(e1.y);
        const __half2* p0 = &g_yh[(size_t)e0.x * (DIM / 2) + h2off];
        const __half2* p1 = &g_yh[(size_t)e1.x * (DIM / 2) + h2off];
        float2 a0 = __half22float2(p0[0]);
        float2 a1 = __half22float2(p0[1]);
        float2 b0 = __half22float2(p1[0]);
        float2 b1 = __half22float2(p1[1]);
        acc0.x += v0 * a0.x; acc0.y += v0 * a0.y;
        acc0.z += v0 * a1.x; acc0.w += v0 * a1.y;
        acc1.x += v1 * b0.x; acc1.y += v1 * b0.y;
        acc1.z += v1 * b1.x; acc1.w += v1 * b1.y;
    }
    if (i < e) {
        int2 e0 = __ldg(&g_edges[i]);
        float v0 = __int_as_float(e0.y);
        const __half2* p0 = &g_yh[(size_t)e0.x * (DIM / 2) + h2off];
        float2 a0 = __half22float2(p0[0]);
        float2 a1 = __half22float2(p0[1]);
        acc0.x += v0 * a0.x; acc0.y += v0 * a0.y;
        acc0.z += v0 * a1.x; acc0.w += v0 * a1.y;
    }
    acc0.x += acc1.x; acc0.y += acc1.y; acc0.z += acc1.z; acc0.w += acc1.w;
    g_xh[(size_t)row * (DIM / 2) + h2off]     = __floats2half2_rn(acc0.x, acc0.y);
    g_xh[(size_t)row * (DIM / 2) + h2off + 1] = __floats2half2_rn(acc0.z, acc0.w);
}

// ---------------- stats: column sums + total sum of squares (reads fp16 Y2) ----------------
__global__ __launch_bounds__(128) void k_reduce() {
    int nb = gridDim.x;
    int rows_per = (N_NODES + nb - 1) / nb;
    int r0 = blockIdx.x * rows_per;
    int r1 = min(r0 + rows_per, N_NODES);
    int t = threadIdx.x;
    float4 acc = make_float4(0.f, 0.f, 0.f, 0.f);
    float sq = 0.f;
    for (int r = r0; r < r1; r++) {
        const __half2* p = &g_xh[(size_t)r * (DIM / 2) + t * 2];
        float2 a = __half22float2(p[0]);
        float2 b = __half22float2(p[1]);
        acc.x += a.x; acc.y += a.y; acc.z += b.x; acc.w += b.y;
        sq += a.x * a.x + a.y * a.y + b.x * b.x + b.y * b.y;
    }
    atomicAdd(&g_colsum[t * 4 + 0], acc.x);
    atomicAdd(&g_colsum[t * 4 + 1], acc.y);
    atomicAdd(&g_colsum[t * 4 + 2], acc.z);
    atomicAdd(&g_colsum[t * 4 + 3], acc.w);
#pragma unroll
    for (int off = 16; off; off >>= 1)
        sq += __shfl_xor_sync(0xffffffffu, sq, off);
    if ((t & 31) == 0) atomicAdd(&g_stats[0], sq);
}

__global__ void k_finalize(const float* __restrict__ scale) {
    __shared__ float red[DIM];
    int t = threadIdx.x;
    float cs = g_colsum[t];
    float mu = cs * (1.0f / N_NODES);
    g_colsum[t] = mu;
    red[t] = cs * mu;
    __syncthreads();
    for (int off = DIM / 2; off; off >>= 1) {
        if (t < off) red[t] += red[t + off];
        __syncthreads();
    }
    if (t == 0) {
        float msq = (g_stats[0] - red[0]) * (1.0f / N_NODES);
        g_stats[1] = rsqrtf(msq) * (1.0f + scale[0]) * 22.627416997969522f;
    }
}

// ---------------- fused center/scale/relu/residual ----------------
__global__ __launch_bounds__(256) void k_final(const float* __restrict__ X,
                                               float* __restrict__ Out) {
    int i = blockIdx.x * blockDim.x + threadIdx.x;
    if (i >= N_NODES * DIM / 4) return;
    float alpha = g_stats[1];
    int d4 = (i & (DIM / 4 - 1)) * 4;
    float4 mu = *(const float4*)&g_colsum[d4];
    const __half2* p = &g_xh[i * 2];
    float2 y01 = __half22float2(p[0]);
    float2 y23 = __half22float2(p[1]);
    float4 xv = *(const float4*)&X[i * 4];
    float4 o;
    o.x = fmaxf((y01.x - mu.x) * alpha, 0.f) + xv.x;
    o.y = fmaxf((y01.y - mu.y) * alpha, 0.f) + xv.y;
    o.z = fmaxf((y23.x - mu.z) * alpha, 0.f) + xv.z;
    o.w = fmaxf((y23.y - mu.w) * alpha, 0.f) + xv.w;
    *(float4*)&Out[i * 4] = o;
}

extern "C" void kernel_launch(void* const* d_in, const int* in_sizes, int n_in,
                              void* d_out, int out_size) {
    const float* x     = (const float*)d_in[0];
    const int*   rows  = (const int*)  d_in[1];
    const int*   cols  = (const int*)  d_in[2];
    const float* vals  = (const float*)d_in[3];
    const float* W     = (const float*)d_in[4];
    const float* scale = (const float*)d_in[5];
    float* out = (float*)d_out;

    // Fork a second stream so the CSR build (atomics/L2) overlaps cvt+GEMM
    // (tensor). kernel_launch runs only a few times (correctness + capture);
    // replays execute the captured graph, so per-call stream/event creation is
    // deterministic and bounded.
    cudaStream_t s2;
    cudaStreamCreate(&s2);
    cudaEvent_t eFork, eJoin;
    cudaEventCreateWithFlags(&eFork, cudaEventDisableTiming);
    cudaEventCreateWithFlags(&eJoin, cudaEventDisableTiming);

    cudaEventRecord(eFork, 0);
    cudaStreamWaitEvent(s2, eFork, 0);

    // branch A (s2): dense path
    k_cvt<<<(NX4 + NW4 + 255) / 256, 256, 0, s2>>>(x, W);
    k_gemm_h<<<dim3(DIM / BN, (N_NODES + BM - 1) / BM), 256, GEMM_SMEM, s2>>>();
    cudaEventRecord(eJoin, s2);

    // branch B (default stream): CSR build
    k_zero<<<(N_NODES + 255) / 256, 256>>>();
    k_hist<<<(N_EDGES + 255) / 256, 256>>>(rows);
    k_scan<<<1, 1024>>>();
    k_scatter<<<(N_EDGES + 255) / 256, 256>>>(rows, cols, vals);

    cudaStreamWaitEvent(0, eJoin, 0);

    k_spmm<<<N_NODES, 128>>>();
    k_reduce<<<512, 128>>>();
    k_finalize<<<1, DIM>>>(scale);
    k_final<<<(N_NODES * DIM / 4 + 255) / 256, 256>>>(x, out);
}

// round 9
// speedup vs baseline: 2.6120x; 1.1527x over previous
#include <cuda_runtime.h>
#include <cuda_fp16.h>
#include <cstdint>

#define N_NODES 50000
#define DIM     512
#define N_EDGES 1600000

// ---- scratch (no allocations allowed -> __device__ globals) ----
__device__ __half2 g_yh[N_NODES * DIM / 2];  // x @ W^T in fp16 (SpMM gather source)
__device__ __half2 g_xh[N_NODES * DIM / 2];  // X in fp16 (GEMM A + residual source)
__device__ __half2 g_y2h[N_NODES * DIM / 2]; // SpMM output in fp16
__device__ __half2 g_wh[DIM * DIM / 2];      // W in fp16 (GEMM B)
__device__ int   g_cnt[N_NODES];
__device__ int   g_start[N_NODES + 1];
__device__ int   g_cursor[N_NODES];
__device__ int2  g_edges[N_EDGES];           // packed (col, val_bits), row-sorted
__device__ float g_colsum[DIM];              // later overwritten with mu[]
__device__ float g_stats[2];                 // [0]=sum of squares, [1]=alpha

// ---------------- CSR build ----------------
__global__ void k_hist(const int* __restrict__ rows) {
    int i = blockIdx.x * blockDim.x + threadIdx.x;
    if (i < N_EDGES) atomicAdd(&g_cnt[rows[i]], 1);
}

__global__ void k_scan() {
    __shared__ int sm[1024];
    int t = threadIdx.x;
    if (t < DIM) g_colsum[t] = 0.f;   // zero stats here (consumed much later)
    if (t == 0)  g_stats[0] = 0.f;
    const int CH = (N_NODES + 1023) / 1024;
    int lo = t * CH;
    int hi = min(lo + CH, N_NODES);
    int sum = 0;
    for (int i = lo; i < hi; i++) sum += g_cnt[i];
    sm[t] = sum;
    __syncthreads();
    for (int off = 1; off < 1024; off <<= 1) {
        int v = (t >= off) ? sm[t - off] : 0;
        __syncthreads();
        sm[t] += v;
        __syncthreads();
    }
    int run = sm[t] - sum;
    for (int i = lo; i < hi; i++) {
        g_start[i]  = run;
        g_cursor[i] = run;
        run += g_cnt[i];
    }
    if (t == 1023) g_start[N_NODES] = sm[1023];
}

__global__ void k_scatter(const int* __restrict__ rows,
                          const int* __restrict__ cols,
                          const float* __restrict__ vals) {
    int i = blockIdx.x * blockDim.x + threadIdx.x;
    if (i < N_EDGES) {
        int r = rows[i];
        int p = atomicAdd(&g_cursor[r], 1);
        g_edges[p] = make_int2(cols[i], __float_as_int(vals[i]));
    }
}

// ---------------- fp32 -> fp16 conversion of X and W ----------------
#define NX4 (N_NODES * DIM / 4)
#define NW4 (DIM * DIM / 4)
__global__ __launch_bounds__(256) void k_cvt(const float* __restrict__ X,
                                             const float* __restrict__ W) {
    int i = blockIdx.x * blockDim.x + threadIdx.x;
    if (i < NX4) {
        float4 v = *(const float4*)&X[i * 4];
        g_xh[i * 2]     = __floats2half2_rn(v.x, v.y);
        g_xh[i * 2 + 1] = __floats2half2_rn(v.z, v.w);
    } else if (i < NX4 + NW4) {
        int j = i - NX4;
        float4 v = *(const float4*)&W[j * 4];
        g_wh[j * 2]     = __floats2half2_rn(v.x, v.y);
        g_wh[j * 2 + 1] = __floats2half2_rn(v.z, v.w);
    }
}

// ================= GEMM: g_yh = X @ W^T via mma.sync f16 + ldmatrix =================
#define BM 128
#define BN 128
#define PADH 40
#define AH_BYTES (128 * PADH * 2)
#define BUFH (2 * AH_BYTES)
#define GEMM_SMEM (2 * BUFH)

__device__ __forceinline__ uint32_t smem_u32(const void* p) {
    uint32_t a;
    asm("{ .reg .u64 t; cvta.to.shared.u64 t, %1; cvt.u32.u64 %0, t; }"
        : "=r"(a) : "l"(p));
    return a;
}

#define CP_ASYNC(dst, src, sz) \
    asm volatile("cp.async.ca.shared.global [%0], [%1], 16, %2;" \
                 :: "r"(dst), "l"(src), "r"(sz))
#define CP_COMMIT()  asm volatile("cp.async.commit_group;")
#define CP_WAIT(N)   asm volatile("cp.async.wait_group %0;" :: "n"(N))

#define LDSM_X4(r0, r1, r2, r3, addr) \
    asm volatile("ldmatrix.sync.aligned.m8n8.x4.shared.b16 {%0,%1,%2,%3}, [%4];" \
                 : "=r"(r0), "=r"(r1), "=r"(r2), "=r"(r3) : "r"(addr))

__device__ __forceinline__ void mma_f16(float* d, uint32_t a0, uint32_t a1,
                                        uint32_t a2, uint32_t a3,
                                        uint32_t b0, uint32_t b1) {
    asm volatile(
        "mma.sync.aligned.m16n8k16.row.col.f32.f16.f16.f32 "
        "{%0,%1,%2,%3}, {%4,%5,%6,%7}, {%8,%9}, {%0,%1,%2,%3};"
        : "+f"(d[0]), "+f"(d[1]), "+f"(d[2]), "+f"(d[3])
        : "r"(a0), "r"(a1), "r"(a2), "r"(a3), "r"(b0), "r"(b1));
}

__global__ void __launch_bounds__(256)
k_gemm_h() {
    extern __shared__ char smem[];
    const int tid  = threadIdx.x;
    const int warp = tid >> 5;
    const int lane = tid & 31;
    const int bm = blockIdx.y * BM;
    const int bn = blockIdx.x * BN;
    const int wm = (warp >> 2) * 64;
    const int wn = (warp & 3) * 32;
    const int g  = lane >> 2;
    const int tg = lane & 3;

    const uint32_t sb = smem_u32(smem);
    const int lrow = tid >> 1;
    const int lpart = tid & 1;

    const int lm_row = lane & 15;
    const int lm_k   = (lane >> 4) * 8;
    const int bl_row = lane & 7;
    const int bl_sel = (lane >> 3) & 1;
    const int bl_nt  = (lane >> 4) & 1;

    const __half* Xh = (const __half*)g_xh;
    const __half* Wh = (const __half*)g_wh;

    float acc[4][4][4];
#pragma unroll
    for (int i = 0; i < 4; i++)
#pragma unroll
        for (int j = 0; j < 4; j++)
#pragma unroll
            for (int k = 0; k < 4; k++) acc[i][j][k] = 0.f;

    auto issue = [&](int kc, int buf) {
        const int k0 = kc * 32;
        const uint32_t abase = sb + buf * BUFH;
        const uint32_t bbase = abase + AH_BYTES;
        {
            int r = bm + lrow;
            uint32_t dst = abase + lrow * (PADH * 2) + lpart * 32;
            const __half* src = &Xh[(size_t)r * DIM + k0 + lpart * 16];
            int ok = (r < N_NODES) ? 16 : 0;
            CP_ASYNC(dst,      src,     ok);
            CP_ASYNC(dst + 16, src + 8, ok);
        }
        {
            uint32_t dst = bbase + lrow * (PADH * 2) + lpart * 32;
            const __half* src = &Wh[(size_t)(bn + lrow) * DIM + k0 + lpart * 16];
            CP_ASYNC(dst,      src,     16);
            CP_ASYNC(dst + 16, src + 8, 16);
        }
        CP_COMMIT();
    };

    issue(0, 0);

    for (int kc = 0; kc < DIM / 32; kc++) {
        if (kc + 1 < DIM / 32) {
            issue(kc + 1, (kc + 1) & 1);
            CP_WAIT(1);
        } else {
            CP_WAIT(0);
        }
        __syncthreads();
        const uint32_t abuf = sb + (kc & 1) * BUFH;
        const uint32_t bbuf = abuf + AH_BYTES;
#pragma unroll
        for (int ks = 0; ks < 2; ks++) {
            const int kb = ks * 16;
            uint32_t a[4][4], b[4][2];
#pragma unroll
            for (int mt = 0; mt < 4; mt++) {
                uint32_t addr = abuf +
                    ((wm + mt * 16 + lm_row) * PADH + kb + lm_k) * 2;
                LDSM_X4(a[mt][0], a[mt][1], a[mt][2], a[mt][3], addr);
            }
#pragma unroll
            for (int np = 0; np < 2; np++) {
                int n0 = wn + (2 * np + bl_nt) * 8 + bl_row;
                uint32_t addr = bbuf + (n0 * PADH + kb + bl_sel * 8) * 2;
                LDSM_X4(b[2 * np][0], b[2 * np][1],
                        b[2 * np + 1][0], b[2 * np + 1][1], addr);
            }
#pragma unroll
            for (int mt = 0; mt < 4; mt++)
#pragma unroll
                for (int nt = 0; nt < 4; nt++)
                    mma_f16(acc[mt][nt], a[mt][0], a[mt][1], a[mt][2], a[mt][3],
                            b[nt][0], b[nt][1]);
        }
        __syncthreads();
    }

#pragma unroll
    for (int mt = 0; mt < 4; mt++) {
#pragma unroll
        for (int nt = 0; nt < 4; nt++) {
            int row = bm + wm + mt * 16 + g;
            int col = bn + wn + nt * 8 + 2 * tg;
            if (row < N_NODES)
                g_yh[((size_t)row * DIM + col) / 2] =
                    __floats2half2_rn(acc[mt][nt][0], acc[mt][nt][1]);
            if (row + 8 < N_NODES)
                g_yh[((size_t)(row + 8) * DIM + col) / 2] =
                    __floats2half2_rn(acc[mt][nt][2], acc[mt][nt][3]);
        }
    }
}

// ---------------- SpMM: g_y2h[r] = sum_e val * yh[col] ----------------
__global__ __launch_bounds__(128) void k_spmm() {
    int row = blockIdx.x;
    int t = threadIdx.x;
    int s = g_start[row];
    int e = g_start[row + 1];
    int h2off = t * 2;
    float4 acc0 = make_float4(0.f, 0.f, 0.f, 0.f);
    float4 acc1 = make_float4(0.f, 0.f, 0.f, 0.f);
    float4 acc2 = make_float4(0.f, 0.f, 0.f, 0.f);
    float4 acc3 = make_float4(0.f, 0.f, 0.f, 0.f);
    int i = s;
    for (; i + 3 < e; i += 4) {
        int2 e0 = __ldg(&g_edges[i]);
        int2 e1 = __ldg(&g_edges[i + 1]);
        int2 e2 = __ldg(&g_edges[i + 2]);
        int2 e3 = __ldg(&g_edges[i + 3]);
        const __half2* p0 = &g_yh[(size_t)e0.x * (DIM / 2) + h2off];
        const __half2* p1 = &g_yh[(size_t)e1.x * (DIM / 2) + h2off];
        const __half2* p2 = &g_yh[(size_t)e2.x * (DIM / 2) + h2off];
        const __half2* p3 = &g_yh[(size_t)e3.x * (DIM / 2) + h2off];
        float v0 = __int_as_float(e0.y), v1 = __int_as_float(e1.y);
        float v2 = __int_as_float(e2.y), v3 = __int_as_float(e3.y);
        float2 a0 = __half22float2(p0[0]), a1 = __half22float2(p0[1]);
        float2 b0 = __half22float2(p1[0]), b1 = __half22float2(p1[1]);
        float2 c0 = __half22float2(p2[0]), c1 = __half22float2(p2[1]);
        float2 d0 = __half22float2(p3[0]), d1 = __half22float2(p3[1]);
        acc0.x += v0 * a0.x; acc0.y += v0 * a0.y; acc0.z += v0 * a1.x; acc0.w += v0 * a1.y;
        acc1.x += v1 * b0.x; acc1.y += v1 * b0.y; acc1.z += v1 * b1.x; acc1.w += v1 * b1.y;
        acc2.x += v2 * c0.x; acc2.y += v2 * c0.y; acc2.z += v2 * c1.x; acc2.w += v2 * c1.y;
        acc3.x += v3 * d0.x; acc3.y += v3 * d0.y; acc3.z += v3 * d1.x; acc3.w += v3 * d1.y;
    }
    for (; i < e; i++) {
        int2 e0 = __ldg(&g_edges[i]);
        float v0 = __int_as_float(e0.y);
        const __half2* p0 = &g_yh[(size_t)e0.x * (DIM / 2) + h2off];
        float2 a0 = __half22float2(p0[0]), a1 = __half22float2(p0[1]);
        acc0.x += v0 * a0.x; acc0.y += v0 * a0.y; acc0.z += v0 * a1.x; acc0.w += v0 * a1.y;
    }
    acc0.x += acc1.x + acc2.x + acc3.x;
    acc0.y += acc1.y + acc2.y + acc3.y;
    acc0.z += acc1.z + acc2.z + acc3.z;
    acc0.w += acc1.w + acc2.w + acc3.w;
    g_y2h[(size_t)row * (DIM / 2) + h2off]     = __floats2half2_rn(acc0.x, acc0.y);
    g_y2h[(size_t)row * (DIM / 2) + h2off + 1] = __floats2half2_rn(acc0.z, acc0.w);
}

// ---------------- stats: column sums + total sum of squares ----------------
__global__ __launch_bounds__(128) void k_reduce() {
    int nb = gridDim.x;
    int rows_per = (N_NODES + nb - 1) / nb;
    int r0 = blockIdx.x * rows_per;
    int r1 = min(r0 + rows_per, N_NODES);
    int t = threadIdx.x;
    float4 acc = make_float4(0.f, 0.f, 0.f, 0.f);
    float sq = 0.f;
    for (int r = r0; r < r1; r++) {
        const __half2* p = &g_y2h[(size_t)r * (DIM / 2) + t * 2];
        float2 a = __half22float2(p[0]);
        float2 b = __half22float2(p[1]);
        acc.x += a.x; acc.y += a.y; acc.z += b.x; acc.w += b.y;
        sq += a.x * a.x + a.y * a.y + b.x * b.x + b.y * b.y;
    }
    atomicAdd(&g_colsum[t * 4 + 0], acc.x);
    atomicAdd(&g_colsum[t * 4 + 1], acc.y);
    atomicAdd(&g_colsum[t * 4 + 2], acc.z);
    atomicAdd(&g_colsum[t * 4 + 3], acc.w);
#pragma unroll
    for (int off = 16; off; off >>= 1)
        sq += __shfl_xor_sync(0xffffffffu, sq, off);
    if ((t & 31) == 0) atomicAdd(&g_stats[0], sq);
}

__global__ void k_finalize(const float* __restrict__ scale) {
    __shared__ float red[DIM];
    int t = threadIdx.x;
    float cs = g_colsum[t];
    float mu = cs * (1.0f / N_NODES);
    g_colsum[t] = mu;
    red[t] = cs * mu;
    __syncthreads();
    for (int off = DIM / 2; off; off >>= 1) {
        if (t < off) red[t] += red[t + off];
        __syncthreads();
    }
    if (t == 0) {
        float msq = (g_stats[0] - red[0]) * (1.0f / N_NODES);
        g_stats[1] = rsqrtf(msq) * (1.0f + scale[0]) * 22.627416997969522f;
    }
}

// ---------------- fused center/scale/relu/residual (fp16 X residual) ----------------
__global__ __launch_bounds__(256) void k_final(float* __restrict__ Out) {
    int i = blockIdx.x * blockDim.x + threadIdx.x;
    if (i >= N_NODES * DIM / 4) return;
    float alpha = g_stats[1];
    int d4 = (i & (DIM / 4 - 1)) * 4;
    float4 mu = *(const float4*)&g_colsum[d4];
    const __half2* py = &g_y2h[i * 2];
    const __half2* px = &g_xh[i * 2];
    float2 y01 = __half22float2(py[0]);
    float2 y23 = __half22float2(py[1]);
    float2 x01 = __half22float2(px[0]);
    float2 x23 = __half22float2(px[1]);
    float4 o;
    o.x = fmaxf((y01.x - mu.x) * alpha, 0.f) + x01.x;
    o.y = fmaxf((y01.y - mu.y) * alpha, 0.f) + x01.y;
    o.z = fmaxf((y23.x - mu.z) * alpha, 0.f) + x23.x;
    o.w = fmaxf((y23.y - mu.w) * alpha, 0.f) + x23.y;
    *(float4*)&Out[i * 4] = o;
}

extern "C" void kernel_launch(void* const* d_in, const int* in_sizes, int n_in,
                              void* d_out, int out_size) {
    const float* x     = (const float*)d_in[0];
    const int*   rows  = (const int*)  d_in[1];
    const int*   cols  = (const int*)  d_in[2];
    const float* vals  = (const float*)d_in[3];
    const float* W     = (const float*)d_in[4];
    const float* scale = (const float*)d_in[5];
    float* out = (float*)d_out;

    // Symmetric two-branch fork. Streams/events are created AND destroyed
    // within this call (destroy is safe: both branches are joined back to the
    // origin stream before we return, and handle destruction is deferred by
    // the driver) so no device memory outlives the run.
    cudaStream_t s2, s3;
    cudaStreamCreate(&s2);
    cudaStreamCreate(&s3);
    cudaEvent_t eFork, eJ2, eJ3;
    cudaEventCreateWithFlags(&eFork, cudaEventDisableTiming);
    cudaEventCreateWithFlags(&eJ2, cudaEventDisableTiming);
    cudaEventCreateWithFlags(&eJ3, cudaEventDisableTiming);

    void* cntp = nullptr;
    cudaGetSymbolAddress(&cntp, g_cnt);

    cudaEventRecord(eFork, 0);
    cudaStreamWaitEvent(s2, eFork, 0);
    cudaStreamWaitEvent(s3, eFork, 0);

    // branch B (s2): CSR build
    cudaMemsetAsync(cntp, 0, N_NODES * sizeof(int), s2);
    k_hist<<<(N_EDGES + 255) / 256, 256, 0, s2>>>(rows);
    k_scan<<<1, 1024, 0, s2>>>();
    k_scatter<<<(N_EDGES + 255) / 256, 256, 0, s2>>>(rows, cols, vals);
    cudaEventRecord(eJ2, s2);

    // branch A (s3): dense path
    k_cvt<<<(NX4 + NW4 + 255) / 256, 256, 0, s3>>>(x, W);
    k_gemm_h<<<dim3(DIM / BN, (N_NODES + BM - 1) / BM), 256, GEMM_SMEM, s3>>>();
    cudaEventRecord(eJ3, s3);

    cudaStreamWaitEvent(0, eJ2, 0);
    cudaStreamWaitEvent(0, eJ3, 0);

    k_spmm<<<N_NODES, 128>>>();
    k_reduce<<<512, 128>>>();
    k_finalize<<<1, DIM>>>(scale);
    k_final<<<(N_NODES * DIM / 4 + 255) / 256, 256>>>(out);

    // release per-call resources so device memory returns to baseline
    cudaEventDestroy(eFork);
    cudaEventDestroy(eJ2);
    cudaEventDestroy(eJ3);
    cudaStreamDestroy(s2);
    cudaStreamDestroy(s3);
}